// round 11
// baseline (speedup 1.0000x reference)
#include <cuda_runtime.h>
#include <cuda_bf16.h>

#define WIN    11
#define HALO   5
#define TILE_H 16
#define NT     128       // thread t owns columns 4t..4t+3
#define IMW    512
#define IMH    512

typedef unsigned long long u64;

// Packed f32x2 ops (sm_103a FFMA2 path — PTX-only, ptxas won't auto-fuse).
#define PACK2(out, lo, hi)   asm("mov.b64 %0, {%1, %2};" : "=l"(out) : "f"(lo), "f"(hi))
#define UNPACK2(lo, hi, in)  asm("mov.b64 {%0, %1}, %2;" : "=f"(lo), "=f"(hi) : "l"(in))
#define ADD2(out, a, b)      asm("add.rn.f32x2 %0, %1, %2;" : "=l"(out) : "l"(a), "l"(b))
#define MUL2(out, a, b)      asm("mul.rn.f32x2 %0, %1, %2;" : "=l"(out) : "l"(a), "l"(b))
#define FMA2(out, a, b, c)   asm("fma.rn.f32x2 %0, %1, %2, %3;" : "=l"(out) : "l"(a), "l"(b), "l"(c))

// packed {-1.f, -1.f} for subtract-via-fma
#define NEG1_F32X2 0xBF800000BF800000ULL

// Horizontal 11-tap sums for 4 consecutive columns.
// sab = packed {sum x, sum y}; sq = packed {sum x^2, sum y^2}; sxy scalar.
struct HS { u64 sab[4]; u64 sq[4]; float sxy[4]; };

__device__ __forceinline__ HS hsums(const float* __restrict__ ra,
                                    const float* __restrict__ rb,
                                    int col0)
{
    float af[20], bf[20];
    #pragma unroll
    for (int k = 0; k < 5; ++k) {
        float4 va = make_float4(0.f, 0.f, 0.f, 0.f);
        float4 vb = va;
        if ((unsigned)(col0 + 4 * k) < IMW) {
            va = *(const float4*)(ra + col0 + 4 * k);
            vb = *(const float4*)(rb + col0 + 4 * k);
        }
        af[4*k+0]=va.x; af[4*k+1]=va.y; af[4*k+2]=va.z; af[4*k+3]=va.w;
        bf[4*k+0]=vb.x; bf[4*k+1]=vb.y; bf[4*k+2]=vb.z; bf[4*k+3]=vb.w;
    }

    // Pack taps j=3..16 (all positions used by the 4 sliding windows).
    u64 P[20];
    #pragma unroll
    for (int j = 3; j < 17; ++j) PACK2(P[j], af[j], bf[j]);

    const u64 neg1 = NEG1_F32X2;
    HS h;

    // initial 11-tap window for column 4t (taps 3..13)
    u64 sab = P[3], sq;
    MUL2(sq, P[3], P[3]);
    float sxy = af[3] * bf[3];
    #pragma unroll
    for (int j = 4; j < 14; ++j) {
        ADD2(sab, sab, P[j]);
        FMA2(sq, P[j], P[j], sq);
        sxy = fmaf(af[j], bf[j], sxy);
    }
    h.sab[0] = sab; h.sq[0] = sq; h.sxy[0] = sxy;

    // slide to columns 4t+1..4t+3 (in tap 13+s, out tap 2+s)
    #pragma unroll
    for (int s = 1; s < 4; ++s) {
        const u64 Pin = P[13+s], Pout = P[2+s];
        ADD2(sab, sab, Pin);
        FMA2(sab, Pout, neg1, sab);
        FMA2(sq, Pin, Pin, sq);
        u64 t2; MUL2(t2, Pout, Pout);
        FMA2(sq, t2, neg1, sq);
        sxy = fmaf(af[13+s], bf[13+s], sxy);
        sxy = fmaf(-af[2+s], bf[2+s], sxy);
        h.sab[s] = sab; h.sq[s] = sq; h.sxy[s] = sxy;
    }
    return h;
}

// No smem, no barriers. Vertical sliding window; leaving row's horizontal
// sums are recomputed from an L1/L2-resident re-read 11 rows back.
__global__ __launch_bounds__(NT, 8) void ssim_kernel(
    const float* __restrict__ img,
    const float* __restrict__ ref,
    const float* __restrict__ drange,
    float* __restrict__ out)
{
    const int t       = threadIdx.x;
    const int b       = blockIdx.x;
    const int rowBase = blockIdx.y * TILE_H;
    const int col0    = 4 * t - 8;

    const float dr    = drange[b];
    // Raw (un-normalized) window sums; fold 121^2 into the constants.
    const float c1    = (0.01f * dr) * (0.01f * dr) * 14641.0f;
    const float c2    = (0.03f * dr) * (0.03f * dr) * 14641.0f;
    const float covn  = 121.0f / 120.0f;
    const float covn2 = 2.0f * covn;
    const u64  neg1   = NEG1_F32X2;

    const size_t base = (size_t)b * IMW * IMH;
    const float* pa = img + base + (long)(rowBase - HALO) * IMW;
    const float* pb = ref + base + (long)(rowBase - HALO) * IMW;
    float*       ro = out + base + (size_t)rowBase * IMW + 4 * t;

    // Vertical accumulators: packed {ax,ay}, packed {axx,ayy}, scalar axy.
    u64 Aab[4], Aq[4];
    float Axy[4];
    #pragma unroll
    for (int c = 0; c < 4; ++c) { Aab[c] = 0ull; Aq[c] = 0ull; Axy[c] = 0.f; }

    for (int i = 0; i < TILE_H + 2 * HALO; ++i) {
        const int gy = rowBase - HALO + i;

        // ---- add incoming row ----
        if ((unsigned)gy < (unsigned)IMH) {
            HS h = hsums(pa, pb, col0);
            #pragma unroll
            for (int c = 0; c < 4; ++c) {
                ADD2(Aab[c], Aab[c], h.sab[c]);
                ADD2(Aq[c],  Aq[c],  h.sq[c]);
                Axy[c] += h.sxy[c];
            }
        }

        // ---- subtract leaving row (11 back), recomputed ----
        const int gys = gy - WIN;
        if (i >= WIN && (unsigned)gys < (unsigned)IMH) {
            HS h = hsums(pa - WIN * IMW, pb - WIN * IMW, col0);
            #pragma unroll
            for (int c = 0; c < 4; ++c) {
                FMA2(Aab[c], h.sab[c], neg1, Aab[c]);
                FMA2(Aq[c],  h.sq[c],  neg1, Aq[c]);
                Axy[c] -= h.sxy[c];
            }
        }
        pa += IMW; pb += IMW;

        // ---- emit output row once 11-row window is complete ----
        if (i >= 2 * HALO) {
            float rr[4];
            #pragma unroll
            for (int c = 0; c < 4; ++c) {
                float Sx, Sy, Sxx, Syy;
                UNPACK2(Sx,  Sy,  Aab[c]);
                UNPACK2(Sxx, Syy, Aq[c]);
                const float Sxy = Axy[c];
                const float p  = Sx * Sy;
                const float xx = Sx * Sx;
                const float yy = Sy * Sy;
                const float A1 = fmaf(2.0f, p, c1);
                const float B1 = xx + yy + c1;
                const float A2 = fmaf(covn2, fmaf(121.0f, Sxy, -p), c2);
                const float vx = fmaf(121.0f, Sxx, -xx);
                const float vy = fmaf(121.0f, Syy, -yy);
                const float B2 = fmaf(covn, vx + vy, c2);
                rr[c] = __fdividef(A1 * A2, B1 * B2);
            }
            *(float4*)ro = make_float4(rr[0], rr[1], rr[2], rr[3]);
            ro += IMW;
        }
    }
}

extern "C" void kernel_launch(void* const* d_in, const int* in_sizes, int n_in,
                              void* d_out, int out_size) {
    const float* img = (const float*)d_in[0];
    const float* ref = (const float*)d_in[1];
    const float* dr  = (const float*)d_in[2];
    float* out = (float*)d_out;

    const int B = in_sizes[2];   // 64

    dim3 grid(B, IMH / TILE_H, 1);   // (64, 32) = 2048 CTAs, 26 input rows each
    ssim_kernel<<<grid, NT>>>(img, ref, dr, out);
}

// round 12
// speedup vs baseline: 1.1044x; 1.1044x over previous
#include <cuda_runtime.h>
#include <cuda_bf16.h>

#define WIN    11
#define HALO   5
#define TILE_H 32
#define NT     64        // thread t owns 8 columns: 8t..8t+7
#define IMW    512
#define IMH    512

// Horizontal 11-tap sums of (x, y, x^2, y^2, x*y) for 8 consecutive columns,
// accumulated (ADD) or subtracted (!ADD) directly into the vertical accums.
// Row pointers point at column 0; col0 = 8t-8. 6 aligned float4 blocks per
// image cover cols [8t-8, 8t+15] ⊇ taps [8t-5, 8t+12].
template<bool ADD>
__device__ __forceinline__ void hsums_acc(const float* __restrict__ ra,
                                          const float* __restrict__ rb,
                                          int col0,
                                          float* __restrict__ ax,  float* __restrict__ ay,
                                          float* __restrict__ axx, float* __restrict__ ayy,
                                          float* __restrict__ axy)
{
    float af[24], bf[24];
    #pragma unroll
    for (int k = 0; k < 6; ++k) {
        float4 va = make_float4(0.f, 0.f, 0.f, 0.f);
        float4 vb = va;
        if ((unsigned)(col0 + 4 * k) < IMW) {
            va = *(const float4*)(ra + col0 + 4 * k);
            vb = *(const float4*)(rb + col0 + 4 * k);
        }
        af[4*k+0]=va.x; af[4*k+1]=va.y; af[4*k+2]=va.z; af[4*k+3]=va.w;
        bf[4*k+0]=vb.x; bf[4*k+1]=vb.y; bf[4*k+2]=vb.z; bf[4*k+3]=vb.w;
    }

    // initial 11-tap sums for column 8t (taps af[3..13])
    float sx=0.f, sy=0.f, sxx=0.f, syy=0.f, sxy=0.f;
    #pragma unroll
    for (int j = 3; j < 14; ++j) {
        const float a = af[j], c = bf[j];
        sx += a; sy += c;
        sxx = fmaf(a, a, sxx);
        syy = fmaf(c, c, syy);
        sxy = fmaf(a, c, sxy);
    }
    if (ADD) { ax[0]+=sx; ay[0]+=sy; axx[0]+=sxx; ayy[0]+=syy; axy[0]+=sxy; }
    else     { ax[0]-=sx; ay[0]-=sy; axx[0]-=sxx; ayy[0]-=syy; axy[0]-=sxy; }

    // slide to columns 8t+1..8t+7 (enter tap 13+s, leave tap 2+s)
    #pragma unroll
    for (int s = 1; s < 8; ++s) {
        const float ai = af[13+s], ao = af[2+s];
        const float bi = bf[13+s], bo = bf[2+s];
        sx += ai - ao;
        sy += bi - bo;
        sxx = fmaf(ai, ai, sxx);  sxx = fmaf(-ao, ao, sxx);
        syy = fmaf(bi, bi, syy);  syy = fmaf(-bo, bo, syy);
        sxy = fmaf(ai, bi, sxy);  sxy = fmaf(-ao, bo, sxy);
        if (ADD) { ax[s]+=sx; ay[s]+=sy; axx[s]+=sxx; ayy[s]+=syy; axy[s]+=sxy; }
        else     { ax[s]-=sx; ay[s]-=sy; axx[s]-=sxx; ayy[s]-=syy; axy[s]-=sxy; }
    }
}

// No smem, no barriers. Vertical sliding window; the leaving row's horizontal
// sums are recomputed from an L1/L2-resident re-read 11 rows back. 8 columns
// per thread cuts halo load amplification (6 float4 blocks for 8 cols vs
// 5 for 4) and amortizes the 11-tap window over 7 slides.
__global__ __launch_bounds__(NT, 8) void ssim_kernel(
    const float* __restrict__ img,
    const float* __restrict__ ref,
    const float* __restrict__ drange,
    float* __restrict__ out)
{
    const int t       = threadIdx.x;
    const int b       = blockIdx.x;
    const int rowBase = blockIdx.y * TILE_H;
    const int col0    = 8 * t - 8;

    const float dr    = drange[b];
    // Raw (un-normalized) window sums; fold 121^2 into the constants.
    const float c1    = (0.01f * dr) * (0.01f * dr) * 14641.0f;
    const float c2    = (0.03f * dr) * (0.03f * dr) * 14641.0f;
    const float covn  = 121.0f / 120.0f;
    const float covn2 = 2.0f * covn;

    const size_t base = (size_t)b * IMW * IMH;
    const float* pa = img + base + (long)(rowBase - HALO) * IMW;   // incoming row
    const float* pb = ref + base + (long)(rowBase - HALO) * IMW;
    float*       ro = out + base + (size_t)rowBase * IMW + 8 * t;

    float ax[8], ay[8], axx[8], ayy[8], axy[8];
    #pragma unroll
    for (int c = 0; c < 8; ++c) { ax[c]=0.f; ay[c]=0.f; axx[c]=0.f; ayy[c]=0.f; axy[c]=0.f; }

    for (int i = 0; i < TILE_H + 2 * HALO; ++i) {
        const int gy = rowBase - HALO + i;

        // ---- add incoming row ----
        if ((unsigned)gy < (unsigned)IMH)
            hsums_acc<true>(pa, pb, col0, ax, ay, axx, ayy, axy);

        // ---- subtract leaving row (added 11 iterations ago), recomputed ----
        const int gys = gy - WIN;
        if (i >= WIN && (unsigned)gys < (unsigned)IMH)
            hsums_acc<false>(pa - WIN * IMW, pb - WIN * IMW, col0, ax, ay, axx, ayy, axy);

        pa += IMW; pb += IMW;

        // ---- emit output row once 11-row window is complete ----
        if (i >= 2 * HALO) {
            float rr[8];
            #pragma unroll
            for (int c = 0; c < 8; ++c) {
                const float Sx = ax[c],  Sy = ay[c];
                const float Sxx = axx[c], Syy = ayy[c], Sxy = axy[c];
                const float p  = Sx * Sy;
                const float xx = Sx * Sx;
                const float yy = Sy * Sy;
                const float A1 = fmaf(2.0f, p, c1);
                const float B1 = xx + yy + c1;
                const float A2 = fmaf(covn2, fmaf(121.0f, Sxy, -p), c2);
                const float vx = fmaf(121.0f, Sxx, -xx);
                const float vy = fmaf(121.0f, Syy, -yy);
                const float B2 = fmaf(covn, vx + vy, c2);
                rr[c] = __fdividef(A1 * A2, B1 * B2);
            }
            *(float4*)(ro)     = make_float4(rr[0], rr[1], rr[2], rr[3]);
            *(float4*)(ro + 4) = make_float4(rr[4], rr[5], rr[6], rr[7]);
            ro += IMW;
        }
    }
}

extern "C" void kernel_launch(void* const* d_in, const int* in_sizes, int n_in,
                              void* d_out, int out_size) {
    const float* img = (const float*)d_in[0];
    const float* ref = (const float*)d_in[1];
    const float* dr  = (const float*)d_in[2];
    float* out = (float*)d_out;

    const int B = in_sizes[2];   // 64

    dim3 grid(B, IMH / TILE_H, 1);   // (64, 16) = 1024 CTAs x 2 warps
    ssim_kernel<<<grid, NT>>>(img, ref, dr, out);
}

// round 14
// speedup vs baseline: 1.1631x; 1.0532x over previous
#include <cuda_runtime.h>
#include <cuda_bf16.h>

#define WIN    11
#define HALO   5
#define TILE_H 16
#define NT     128       // thread t owns columns 4t..4t+3
#define IMW    512
#define IMH    512

// Horizontal 11-tap sums of (x, y, x^2, y^2, x*y) for 4 consecutive columns,
// accumulated (ADD) or subtracted (!ADD) into the vertical accumulators.
// Needed taps: cols [4t-5, 4t+8] = 14 floats per image. Loaded as
// scalar(4t-5) + float4(4t-4) + float4(4t) + float4(4t+4) + scalar(4t+8):
// exactly the needed 14 floats (round-10 fetched 20).
template<bool ADD>
__device__ __forceinline__ void hsums_acc(const float* __restrict__ ra,
                                          const float* __restrict__ rb,
                                          int t,
                                          float* __restrict__ ax,  float* __restrict__ ay,
                                          float* __restrict__ axx, float* __restrict__ ayy,
                                          float* __restrict__ axy)
{
    const int c_m5 = 4*t - 5, c_m4 = 4*t - 4, c_0 = 4*t, c_p4 = 4*t + 4, c_p8 = 4*t + 8;

    float af[14], bf[14];

    af[0]  = ((unsigned)c_m5 < IMW) ? ra[c_m5] : 0.f;
    bf[0]  = ((unsigned)c_m5 < IMW) ? rb[c_m5] : 0.f;
    af[13] = ((unsigned)c_p8 < IMW) ? ra[c_p8] : 0.f;
    bf[13] = ((unsigned)c_p8 < IMW) ? rb[c_p8] : 0.f;

    {
        float4 va = make_float4(0.f,0.f,0.f,0.f), vb = va;
        if ((unsigned)c_m4 < IMW) { va = *(const float4*)(ra + c_m4); vb = *(const float4*)(rb + c_m4); }
        af[1]=va.x; af[2]=va.y; af[3]=va.z; af[4]=va.w;
        bf[1]=vb.x; bf[2]=vb.y; bf[3]=vb.z; bf[4]=vb.w;
    }
    {
        float4 va = make_float4(0.f,0.f,0.f,0.f), vb = va;
        if ((unsigned)c_0 < IMW) { va = *(const float4*)(ra + c_0); vb = *(const float4*)(rb + c_0); }
        af[5]=va.x; af[6]=va.y; af[7]=va.z; af[8]=va.w;
        bf[5]=vb.x; bf[6]=vb.y; bf[7]=vb.z; bf[8]=vb.w;
    }
    {
        float4 va = make_float4(0.f,0.f,0.f,0.f), vb = va;
        if ((unsigned)c_p4 < IMW) { va = *(const float4*)(ra + c_p4); vb = *(const float4*)(rb + c_p4); }
        af[9]=va.x;  af[10]=va.y; af[11]=va.z; af[12]=va.w;
        bf[9]=vb.x;  bf[10]=vb.y; bf[11]=vb.z; bf[12]=vb.w;
    }

    // initial 11-tap window for column 4t (taps af[0..10])
    float sx=0.f, sy=0.f, sxx=0.f, syy=0.f, sxy=0.f;
    #pragma unroll
    for (int j = 0; j < 11; ++j) {
        const float a = af[j], c = bf[j];
        sx += a; sy += c;
        sxx = fmaf(a, a, sxx);
        syy = fmaf(c, c, syy);
        sxy = fmaf(a, c, sxy);
    }
    if (ADD) { ax[0]+=sx; ay[0]+=sy; axx[0]+=sxx; ayy[0]+=syy; axy[0]+=sxy; }
    else     { ax[0]-=sx; ay[0]-=sy; axx[0]-=sxx; ayy[0]-=syy; axy[0]-=sxy; }

    // slide to columns 4t+1..4t+3 (enter af[10+s], leave af[s-1])
    #pragma unroll
    for (int s = 1; s < 4; ++s) {
        const float ai = af[10+s], ao = af[s-1];
        const float bi = bf[10+s], bo = bf[s-1];
        sx += ai - ao;
        sy += bi - bo;
        sxx = fmaf(ai, ai, sxx);  sxx = fmaf(-ao, ao, sxx);
        syy = fmaf(bi, bi, syy);  syy = fmaf(-bo, bo, syy);
        sxy = fmaf(ai, bi, sxy);  sxy = fmaf(-ao, bo, sxy);
        if (ADD) { ax[s]+=sx; ay[s]+=sy; axx[s]+=sxx; ayy[s]+=syy; axy[s]+=sxy; }
        else     { ax[s]-=sx; ay[s]-=sy; axx[s]-=sxx; ayy[s]-=syy; axy[s]-=sxy; }
    }
}

// No smem, no barriers. Vertical sliding window; the leaving row's horizontal
// sums are recomputed from an L1/L2-resident re-read 11 rows back.
// TILE_H=16: 2048 CTAs -> occupancy pins at the 58-reg limit (~8 CTAs/SM).
__global__ __launch_bounds__(NT) void ssim_kernel(
    const float* __restrict__ img,
    const float* __restrict__ ref,
    const float* __restrict__ drange,
    float* __restrict__ out)
{
    const int t       = threadIdx.x;
    const int b       = blockIdx.x;
    const int rowBase = blockIdx.y * TILE_H;

    const float dr    = drange[b];
    // Raw (un-normalized) window sums; fold 121^2 into the constants.
    const float c1    = (0.01f * dr) * (0.01f * dr) * 14641.0f;
    const float c2    = (0.03f * dr) * (0.03f * dr) * 14641.0f;
    const float covn  = 121.0f / 120.0f;
    const float covn2 = 2.0f * covn;

    const size_t base = (size_t)b * IMW * IMH;
    const float* pa = img + base + (long)(rowBase - HALO) * IMW;   // incoming row
    const float* pb = ref + base + (long)(rowBase - HALO) * IMW;
    float*       ro = out + base + (size_t)rowBase * IMW + 4 * t;

    float ax[4], ay[4], axx[4], ayy[4], axy[4];
    #pragma unroll
    for (int c = 0; c < 4; ++c) { ax[c]=0.f; ay[c]=0.f; axx[c]=0.f; ayy[c]=0.f; axy[c]=0.f; }

    for (int i = 0; i < TILE_H + 2 * HALO; ++i) {
        const int gy = rowBase - HALO + i;

        // ---- add incoming row ----
        if ((unsigned)gy < (unsigned)IMH)
            hsums_acc<true>(pa, pb, t, ax, ay, axx, ayy, axy);

        // ---- subtract leaving row (added 11 iterations ago), recomputed ----
        const int gys = gy - WIN;
        if (i >= WIN && (unsigned)gys < (unsigned)IMH)
            hsums_acc<false>(pa - WIN * IMW, pb - WIN * IMW, t, ax, ay, axx, ayy, axy);

        pa += IMW; pb += IMW;

        // ---- emit output row once 11-row window is complete ----
        if (i >= 2 * HALO) {
            float rr[4];
            #pragma unroll
            for (int c = 0; c < 4; ++c) {
                const float Sx = ax[c],  Sy = ay[c];
                const float Sxx = axx[c], Syy = ayy[c], Sxy = axy[c];
                const float p  = Sx * Sy;
                const float xx = Sx * Sx;
                const float yy = Sy * Sy;
                const float A1 = fmaf(2.0f, p, c1);
                const float B1 = xx + yy + c1;
                const float A2 = fmaf(covn2, fmaf(121.0f, Sxy, -p), c2);
                const float vx = fmaf(121.0f, Sxx, -xx);
                const float vy = fmaf(121.0f, Syy, -yy);
                const float B2 = fmaf(covn, vx + vy, c2);
                rr[c] = __fdividef(A1 * A2, B1 * B2);
            }
            *(float4*)ro = make_float4(rr[0], rr[1], rr[2], rr[3]);
            ro += IMW;
        }
    }
}

extern "C" void kernel_launch(void* const* d_in, const int* in_sizes, int n_in,
                              void* d_out, int out_size) {
    const float* img = (const float*)d_in[0];
    const float* ref = (const float*)d_in[1];
    const float* dr  = (const float*)d_in[2];
    float* out = (float*)d_out;

    const int B = in_sizes[2];   // 64

    dim3 grid(B, IMH / TILE_H, 1);   // (64, 32) = 2048 CTAs, 26 input rows each
    ssim_kernel<<<grid, NT>>>(img, ref, dr, out);
}